// round 1
// baseline (speedup 1.0000x reference)
#include <cuda_runtime.h>
#include <cstdint>

#define BATCH  32
#define NODES  20000
#define FEAT   64
#define OUTF   64
#define EIG    16

#define NCHUNK 20          // node chunks for stage-1 partial reduction
#define MCHUNK (NODES / NCHUNK)   // 1000 nodes per chunk
#define TILE   128         // smem V tile (rows)

#define NCH3   40          // node chunks for stage-3
#define NPB3   (NODES / NCH3)     // 500 nodes per block

typedef unsigned long long ull;

// Scratch (device globals; no allocation allowed)
__device__ __align__(16) float zpart_g[BATCH * NCHUNK * FEAT * EIG]; // 2.6 MB
__device__ __align__(16) float z_g[BATCH * FEAT * EIG];              // 128 KB
__device__ __align__(16) float w_g[BATCH * OUTF * EIG];              // 128 KB

// ---- packed f32x2 helpers (Blackwell-only; ptxas won't auto-fuse) ----
__device__ __forceinline__ ull ffma2(ull a, ull b, ull c) {
    ull d;
    asm("fma.rn.f32x2 %0, %1, %2, %3;" : "=l"(d) : "l"(a), "l"(b), "l"(c));
    return d;
}
__device__ __forceinline__ ull fadd2(ull a, ull b) {
    ull d;
    asm("add.rn.f32x2 %0, %1, %2;" : "=l"(d) : "l"(a), "l"(b));
    return d;
}
__device__ __forceinline__ ull pack2(float x) {
    ull d;
    asm("mov.b64 %0, {%1, %1};" : "=l"(d) : "f"(x));
    return d;
}
__device__ __forceinline__ float hsum2(ull a) {
    float lo, hi;
    asm("mov.b64 {%0, %1}, %2;" : "=f"(lo), "=f"(hi) : "l"(a));
    return lo + hi;
}

// ============================================================================
// Kernel 1: zpart[b][chunk][i][f] = sum_{m in chunk} V[m,f] * x[b,m,i]
// grid (NCHUNK, BATCH), 256 threads: it = i (0..63), ms = m-sublane (0..3)
// ============================================================================
__global__ void __launch_bounds__(256) k1_project(const float* __restrict__ x,
                                                  const float* __restrict__ V) {
    __shared__ ulonglong2 Vs[TILE][4];   // V tile as f32x2 pairs, 8 KB
    __shared__ ull red[FEAT][8];         // cross-ms reduction, 4 KB

    const int tid   = threadIdx.x;
    const int b     = blockIdx.y;
    const int chunk = blockIdx.x;
    const int m0    = chunk * MCHUNK;
    const int it    = tid & 63;
    const int ms    = tid >> 6;

    const float* xb = x + ((size_t)b * NODES + m0) * FEAT + it;

    ull acc[8];
#pragma unroll
    for (int p = 0; p < 8; ++p) acc[p] = 0ULL;

    for (int tbase = 0; tbase < MCHUNK; tbase += TILE) {
        int valid = MCHUNK - tbase;
        if (valid > TILE) valid = TILE;

        // cooperative V tile load (coalesced 16B)
        for (int idx = tid; idx < TILE * 4; idx += 256) {
            int ml = idx >> 2, p = idx & 3;
            ulonglong2 v = make_ulonglong2(0ULL, 0ULL);
            if (ml < valid)
                v = ((const ulonglong2*)(V + (size_t)(m0 + tbase + ml) * EIG))[p];
            Vs[ml][p] = v;
        }
        __syncthreads();

#pragma unroll 4
        for (int ml = ms; ml < TILE; ml += 4) {
            float xv = (ml < valid) ? xb[(size_t)(tbase + ml) * FEAT] : 0.0f;
            ull x2 = pack2(xv);
            ulonglong2 q0 = Vs[ml][0];
            ulonglong2 q1 = Vs[ml][1];
            ulonglong2 q2 = Vs[ml][2];
            ulonglong2 q3 = Vs[ml][3];
            acc[0] = ffma2(q0.x, x2, acc[0]);
            acc[1] = ffma2(q0.y, x2, acc[1]);
            acc[2] = ffma2(q1.x, x2, acc[2]);
            acc[3] = ffma2(q1.y, x2, acc[3]);
            acc[4] = ffma2(q2.x, x2, acc[4]);
            acc[5] = ffma2(q2.y, x2, acc[5]);
            acc[6] = ffma2(q3.x, x2, acc[6]);
            acc[7] = ffma2(q3.y, x2, acc[7]);
        }
        __syncthreads();
    }

    // reduce the 4 ms-sublanes (deterministic ordered passes)
    for (int s = 0; s < 4; ++s) {
        if (ms == s) {
#pragma unroll
            for (int p = 0; p < 8; ++p)
                red[it][p] = (s == 0) ? acc[p] : fadd2(red[it][p], acc[p]);
        }
        __syncthreads();
    }

    ull* zp = (ull*)(zpart_g + ((size_t)b * NCHUNK + chunk) * (FEAT * EIG));
    const ull* rp = (const ull*)red;
    for (int idx = tid; idx < FEAT * 8; idx += 256) zp[idx] = rp[idx];
}

// ============================================================================
// Kernel 1b: z[b][i][f] = sum_c zpart[b][c][i][f]      grid 32 x 256
// ============================================================================
__global__ void __launch_bounds__(256) k1b_reduce() {
    int idx = blockIdx.x * 256 + threadIdx.x;  // 0..8191 float4 slots
    int b = idx >> 8, q = idx & 255;
    const float4* zp = (const float4*)zpart_g;
    float4 s = make_float4(0.f, 0.f, 0.f, 0.f);
#pragma unroll
    for (int c = 0; c < NCHUNK; ++c) {
        float4 v = zp[((size_t)b * NCHUNK + c) * 256 + q];
        s.x += v.x; s.y += v.y; s.z += v.z; s.w += v.w;
    }
    ((float4*)z_g)[(size_t)b * 256 + q] = s;
}

// ============================================================================
// Kernel 2: w[b][j][e] = sum_{i,f} G[j,i,e,f] * z[b,i,f]
// One warp per (c = j*16+e, batch-group of 8).  grid 512 x 256 (4096 warps)
// ============================================================================
__global__ void __launch_bounds__(256) k2_mix(const float* __restrict__ G) {
    const int lane = threadIdx.x & 31;
    const int W    = blockIdx.x * 8 + (threadIdx.x >> 5);
    const int c    = W >> 2;      // 0..1023 output column (j,e)
    const int bg   = W & 3;       // batch group 0..3 (8 batches each)
    const int j    = c >> 4;
    const int e    = c & 15;

    const float4* Gp = (const float4*)(G + (size_t)j * (FEAT * EIG * EIG) + (size_t)e * EIG);
    const float4* zb = (const float4*)z_g;
    const int i0 = lane >> 2, fq = lane & 3;

    float acc[8];
#pragma unroll
    for (int r = 0; r < 8; ++r) acc[r] = 0.f;

#pragma unroll
    for (int s = 0; s < 8; ++s) {
        int i  = s * 8 + i0;
        float4 g = Gp[(size_t)i * 64 + fq];        // G[j,i,e,4fq..4fq+3]
        int kq = i * 4 + fq;                        // float4 index into z row
#pragma unroll
        for (int r = 0; r < 8; ++r) {
            float4 zv = zb[(size_t)(bg * 8 + r) * 256 + kq];
            acc[r] = fmaf(g.x, zv.x, fmaf(g.y, zv.y, fmaf(g.z, zv.z, fmaf(g.w, zv.w, acc[r]))));
        }
    }
#pragma unroll
    for (int r = 0; r < 8; ++r) {
#pragma unroll
        for (int off = 16; off; off >>= 1)
            acc[r] += __shfl_xor_sync(0xffffffffu, acc[r], off);
    }
    if (lane == 0) {
#pragma unroll
        for (int r = 0; r < 8; ++r)
            w_g[(size_t)(bg * 8 + r) * 1024 + c] = acc[r];
    }
}

// ============================================================================
// Kernel 3: out[b,n,j] = sum_e V[n,e] * w[b,j,e]
// grid (NCH3, BATCH), 256 threads: jt = j (0..63), ns = node-sublane (0..3)
// ============================================================================
__global__ void __launch_bounds__(256) k3_expand(const float* __restrict__ V,
                                                 float* __restrict__ out) {
    __shared__ ulonglong2 Vs[TILE][4];

    const int tid = threadIdx.x;
    const int b   = blockIdx.y;
    const int n0  = blockIdx.x * NPB3;
    const int jt  = tid & 63;
    const int ns  = tid >> 6;

    // w row for this thread's j, as 8 f32x2 pairs over e
    ull wreg[8];
    const ull* wp = (const ull*)(w_g + ((size_t)b * OUTF + jt) * EIG);
#pragma unroll
    for (int p = 0; p < 8; ++p) wreg[p] = wp[p];

    float* ob = out + ((size_t)b * NODES + n0) * OUTF + jt;

    for (int tbase = 0; tbase < NPB3; tbase += TILE) {
        int valid = NPB3 - tbase;
        if (valid > TILE) valid = TILE;

        for (int idx = tid; idx < TILE * 4; idx += 256) {
            int nl = idx >> 2, p = idx & 3;
            if (nl < valid)
                Vs[nl][p] = ((const ulonglong2*)(V + (size_t)(n0 + tbase + nl) * EIG))[p];
        }
        __syncthreads();

#pragma unroll 2
        for (int nl = ns; nl < valid; nl += 4) {
            ulonglong2 q0 = Vs[nl][0];
            ulonglong2 q1 = Vs[nl][1];
            ulonglong2 q2 = Vs[nl][2];
            ulonglong2 q3 = Vs[nl][3];
            ull a0 = ffma2(wreg[0], q0.x, 0ULL);
            ull a1 = ffma2(wreg[1], q0.y, 0ULL);
            a0 = ffma2(wreg[2], q1.x, a0);
            a1 = ffma2(wreg[3], q1.y, a1);
            a0 = ffma2(wreg[4], q2.x, a0);
            a1 = ffma2(wreg[5], q2.y, a1);
            a0 = ffma2(wreg[6], q3.x, a0);
            a1 = ffma2(wreg[7], q3.y, a1);
            float o = hsum2(fadd2(a0, a1));
            ob[(size_t)(tbase + nl) * OUTF] = o;
        }
        __syncthreads();
    }
}

// ============================================================================
extern "C" void kernel_launch(void* const* d_in, const int* in_sizes, int n_in,
                              void* d_out, int out_size) {
    const float* x = (const float*)d_in[0];   // (32, 20000, 64)
    const float* V = (const float*)d_in[1];   // (20000, 16)
    const float* G = (const float*)d_in[2];   // (64, 64, 16, 16)
    float* out = (float*)d_out;               // (32, 20000, 64)

    k1_project<<<dim3(NCHUNK, BATCH), 256>>>(x, V);
    k1b_reduce<<<32, 256>>>();
    k2_mix<<<512, 256>>>(G);
    k3_expand<<<dim3(NCH3, BATCH), 256>>>(V, out);
}